// round 7
// baseline (speedup 1.0000x reference)
#include <cuda_runtime.h>
#include <cuda_fp16.h>
#include <math.h>

#define N_NODES 50000
#define N_PAD   50048           // 782 * 64
#define N_EDGES 640000
#define IN_DIM 5
#define HID 128
#define NUM_GRAPHS 512

// ---------------- device scratch (static, no allocation) ----------------
// cat[n][0:128] = agg, cat[n][128:256] = h ; hi/lo fp16 split (hi+lo ~= fp32)
__device__ __align__(16) __half g_cath[(size_t)N_PAD * 256];
__device__ __align__(16) __half g_catl[(size_t)N_PAD * 256];
__device__ __align__(16) __half g_W1hi[256 * HID], g_W1lo[256 * HID];
__device__ __align__(16) __half g_W2hi[256 * HID], g_W2lo[256 * HID];
__device__ __align__(16) float  g_agg0[N_NODES * IN_DIM];
__device__ float g_pooled[NUM_GRAPHS * HID];
__device__ int   g_deg   [N_NODES];
__device__ int   g_rowptr[N_NODES + 1];
__device__ int   g_cursor[N_NODES];
__device__ int   g_csr_src[N_EDGES];
__device__ int   g_cnt   [NUM_GRAPHS];

// split helpers
__device__ __forceinline__ void split2(float v0, float v1, unsigned& hi, unsigned& lo) {
    __half2 h = __floats2half2_rn(v0, v1);
    float2 hf = __half22float2(h);
    __half2 l = __floats2half2_rn(v0 - hf.x, v1 - hf.y);
    hi = *(unsigned*)&h;
    lo = *(unsigned*)&l;
}

// ---------------- zero init (+ zero pad rows of cat hi/lo) ----------------
__global__ void k_zero() {
    int i = blockIdx.x * blockDim.x + threadIdx.x;
    if (i < N_NODES) g_deg[i] = 0;
    if (i < NUM_GRAPHS * HID) g_pooled[i] = 0.0f;
    if (i < NUM_GRAPHS) g_cnt[i] = 0;
    if (i < (N_PAD - N_NODES) * 256 / 2) {    // 48 pad rows, as uint
        ((unsigned*)(g_cath + (size_t)N_NODES * 256))[i] = 0u;
        ((unsigned*)(g_catl + (size_t)N_NODES * 256))[i] = 0u;
    }
}

// ---------------- CSR build ----------------
__global__ void k_hist(const int* __restrict__ ei) {
    int e = blockIdx.x * blockDim.x + threadIdx.x;
    if (e < N_EDGES) atomicAdd(&g_deg[ei[N_EDGES + e]], 1);
}

__global__ void k_scan() {
    __shared__ int sums[1024];
    int t = threadIdx.x;
    const int CH = (N_NODES + 1023) / 1024;
    int start = t * CH;
    int end = start + CH; if (end > N_NODES) end = N_NODES;
    int s = 0;
    for (int i = start; i < end; i++) s += g_deg[i];
    sums[t] = s;
    __syncthreads();
    for (int off = 1; off < 1024; off <<= 1) {
        int v = (t >= off) ? sums[t - off] : 0;
        __syncthreads();
        sums[t] += v;
        __syncthreads();
    }
    int base = (t == 0) ? 0 : sums[t - 1];
    for (int i = start; i < end; i++) {
        int d = g_deg[i];
        g_rowptr[i] = base;
        g_cursor[i] = base;
        base += d;
    }
    if (t == 1023) g_rowptr[N_NODES] = sums[1023];
}

__global__ void k_scatter(const int* __restrict__ ei) {
    int e = blockIdx.x * blockDim.x + threadIdx.x;
    if (e < N_EDGES) {
        int d = ei[N_EDGES + e];
        int p = atomicAdd(&g_cursor[d], 1);
        g_csr_src[p] = ei[e];
    }
}

__global__ void k_cnt(const int* __restrict__ batch) {
    int i = blockIdx.x * blockDim.x + threadIdx.x;
    if (i < N_NODES) atomicAdd(&g_cnt[batch[i]], 1);
}

// ---------------- weight conversion: stacked [Wrel; Wroot] -> fp16 hi/lo ----
__global__ void k_wconv(const float* __restrict__ Wrel1, const float* __restrict__ Wroot1,
                        const float* __restrict__ Wrel2, const float* __restrict__ Wroot2) {
    int i = blockIdx.x * blockDim.x + threadIdx.x;   // 2 * 256 * 128
    if (i >= 2 * 256 * HID) return;
    int layer = i >> 15;
    int j = i & 32767;
    int r = j >> 7, c = j & 127;
    const float* Wr = layer ? Wrel2 : Wrel1;
    const float* Wo = layer ? Wroot2 : Wroot1;
    float v = (r < 128) ? Wr[r * HID + c] : Wo[(r - 128) * HID + c];
    __half hi = __float2half_rn(v);
    __half lo = __float2half_rn(v - __half2float(hi));
    if (layer) { g_W2hi[j] = hi; g_W2lo[j] = lo; }
    else       { g_W1hi[j] = hi; g_W1lo[j] = lo; }
}

// ---------------- layer 0 (IN_DIM = 5) ----------------
__global__ void k_agg0(const float* __restrict__ x) {
    int n = blockIdx.x * blockDim.x + threadIdx.x;
    if (n >= N_NODES) return;
    float s0 = 0.f, s1 = 0.f, s2 = 0.f, s3 = 0.f, s4 = 0.f;
    int beg = g_rowptr[n], end = g_rowptr[n + 1];
    for (int j = beg; j < end; j++) {
        const float* xr = x + (size_t)g_csr_src[j] * IN_DIM;
        s0 += xr[0]; s1 += xr[1]; s2 += xr[2]; s3 += xr[3]; s4 += xr[4];
    }
    float* o = g_agg0 + (size_t)n * IN_DIM;
    o[0] = s0; o[1] = s1; o[2] = s2; o[3] = s3; o[4] = s4;
}

__global__ void k_h0(const float* __restrict__ x,
                     const float* __restrict__ Wrel, const float* __restrict__ brel,
                     const float* __restrict__ Wroot) {
    __shared__ float sa[IN_DIM], sx[IN_DIM];
    int n = blockIdx.x;
    int c = threadIdx.x;              // 128 threads
    if (c < IN_DIM) {
        sa[c] = g_agg0[(size_t)n * IN_DIM + c];
        sx[c] = x[(size_t)n * IN_DIM + c];
    }
    __syncthreads();
    float v = brel[c];
#pragma unroll
    for (int k = 0; k < IN_DIM; k++) {
        v = fmaf(sa[k], Wrel[k * HID + c], v);
        v = fmaf(sx[k], Wroot[k * HID + c], v);
    }
    v = fmaxf(v, 0.0f);
    __half hi = __float2half_rn(v);
    __half lo = __float2half_rn(v - __half2float(hi));
    g_cath[(size_t)n * 256 + 128 + c] = hi;
    g_catl[(size_t)n * 256 + 128 + c] = lo;
}

// ---------------- edge aggregation, warp per node ----------------
// reads hi half of h-slot; writes agg slot hi/lo (exact split of fp32 sum)
__global__ void k_gather() {
    int node = (blockIdx.x * blockDim.x + threadIdx.x) >> 5;
    int lane = threadIdx.x & 31;
    if (node >= N_NODES) return;
    float a0 = 0.f, a1 = 0.f, a2 = 0.f, a3 = 0.f;
    int beg = g_rowptr[node], end = g_rowptr[node + 1];
    int j = beg;
    for (; j + 1 < end; j += 2) {
        int s0 = g_csr_src[j], s1 = g_csr_src[j + 1];
        uint2 p0 = __ldg((const uint2*)(g_cath + (size_t)s0 * 256 + 128) + lane);
        uint2 p1 = __ldg((const uint2*)(g_cath + (size_t)s1 * 256 + 128) + lane);
        float2 f0 = __half22float2(*(__half2*)&p0.x);
        float2 f1 = __half22float2(*(__half2*)&p0.y);
        float2 q0 = __half22float2(*(__half2*)&p1.x);
        float2 q1 = __half22float2(*(__half2*)&p1.y);
        a0 += f0.x + q0.x; a1 += f0.y + q0.y;
        a2 += f1.x + q1.x; a3 += f1.y + q1.y;
    }
    if (j < end) {
        int s0 = g_csr_src[j];
        uint2 p0 = __ldg((const uint2*)(g_cath + (size_t)s0 * 256 + 128) + lane);
        float2 f0 = __half22float2(*(__half2*)&p0.x);
        float2 f1 = __half22float2(*(__half2*)&p0.y);
        a0 += f0.x; a1 += f0.y; a2 += f1.x; a3 += f1.y;
    }
    unsigned h01, l01, h23, l23;
    split2(a0, a1, h01, l01);
    split2(a2, a3, h23, l23);
    *((uint2*)(g_cath + (size_t)node * 256) + lane) = make_uint2(h01, h23);
    *((uint2*)(g_catl + (size_t)node * 256) + lane) = make_uint2(l01, l23);
}

// ---------------- split-fp16 tensor-core GEMM -----------------
// D = Ah*Wh + Ah*Wl + Al*Wh  (fp32 accumulate) ~ fp32-precision GEMM
__device__ __forceinline__ void mma16816(float* c, const unsigned* a,
                                         unsigned b0, unsigned b1) {
    asm volatile("mma.sync.aligned.m16n8k16.row.col.f32.f16.f16.f32 "
                 "{%0,%1,%2,%3}, {%4,%5,%6,%7}, {%8,%9}, {%0,%1,%2,%3};"
                 : "+f"(c[0]), "+f"(c[1]), "+f"(c[2]), "+f"(c[3])
                 : "r"(a[0]), "r"(a[1]), "r"(a[2]), "r"(a[3]), "r"(b0), "r"(b1));
}

#define LDMX4(dst, ptr)                                                          \
    { unsigned _ad = (unsigned)__cvta_generic_to_shared(ptr);                    \
      asm volatile("ldmatrix.sync.aligned.m8n8.x4.shared.b16 {%0,%1,%2,%3}, [%4];" \
                   : "=r"(dst[0]), "=r"(dst[1]), "=r"(dst[2]), "=r"(dst[3]) : "r"(_ad)); }
#define LDMX4T(dst, ptr)                                                         \
    { unsigned _ad = (unsigned)__cvta_generic_to_shared(ptr);                    \
      asm volatile("ldmatrix.sync.aligned.m8n8.x4.trans.shared.b16 {%0,%1,%2,%3}, [%4];" \
                   : "=r"(dst[0]), "=r"(dst[1]), "=r"(dst[2]), "=r"(dst[3]) : "r"(_ad)); }

// POOL==0: weights W1, relu, write h-slot hi/lo. POOL==1: weights W2, pool.
template <int POOL>
__global__ __launch_bounds__(128, 4)
void k_gemm(const float* __restrict__ bias, const int* __restrict__ batch) {
    __shared__ __half Ahs[64][24], Als[64][24];     // 64 rows x 16 k (+8 pad)
    __shared__ __half Whs[16][136], Wls[16][136];   // 16 k x 128 n (+8 pad)

    const __half* __restrict__ WH = POOL ? g_W2hi : g_W1hi;
    const __half* __restrict__ WL = POOL ? g_W2lo : g_W1lo;

    const int tid = threadIdx.x;
    const int lane = tid & 31;
    const int w = tid >> 5;           // warp w -> rows [w*16, w*16+16)
    const int row0 = blockIdx.x * 64;

    float c[16][4];
#pragma unroll
    for (int t = 0; t < 16; t++)
#pragma unroll
        for (int q = 0; q < 4; q++) c[t][q] = 0.0f;

    const int a_row = w * 16 + (lane & 15);
    const int a_co = (lane >> 4) << 3;
    const int b_kr = (lane & 7) + (((lane >> 3) & 1) << 3);
    const int b_no = (lane >> 4) << 3;

    for (int kc = 0; kc < 16; kc++) {
        int k0 = kc * 16;
        __syncthreads();
        // A chunk: 64 rows x 16 halfs, hi & lo (1 uint4 pair per thread)
        {
            int r = tid >> 1, seg = tid & 1;
            *(uint4*)&Ahs[r][seg * 8] =
                *(const uint4*)(g_cath + (size_t)(row0 + r) * 256 + k0 + seg * 8);
            *(uint4*)&Als[r][seg * 8] =
                *(const uint4*)(g_catl + (size_t)(row0 + r) * 256 + k0 + seg * 8);
        }
        // W chunk: 16 x 128, hi & lo
#pragma unroll
        for (int i = 0; i < 2; i++) {
            int idx = tid + i * 128;
            int r = idx >> 4, seg = idx & 15;
            *(uint4*)&Whs[r][seg * 8] = *(const uint4*)(WH + (size_t)(k0 + r) * HID + seg * 8);
            *(uint4*)&Wls[r][seg * 8] = *(const uint4*)(WL + (size_t)(k0 + r) * HID + seg * 8);
        }
        __syncthreads();

        unsigned ah[4], al[4];
        LDMX4(ah, &Ahs[a_row][a_co]);
        LDMX4(al, &Als[a_row][a_co]);
#pragma unroll
        for (int t = 0; t < 8; t++) {
            unsigned bh[4], bl[4];
            LDMX4T(bh, &Whs[b_kr][t * 16 + b_no]);
            LDMX4T(bl, &Wls[b_kr][t * 16 + b_no]);
            mma16816(c[2 * t],     ah, bh[0], bh[1]);
            mma16816(c[2 * t],     ah, bl[0], bl[1]);
            mma16816(c[2 * t],     al, bh[0], bh[1]);
            mma16816(c[2 * t + 1], ah, bh[2], bh[3]);
            mma16816(c[2 * t + 1], ah, bl[2], bl[3]);
            mma16816(c[2 * t + 1], al, bh[2], bh[3]);
        }
    }

    // epilogue
    const int r0 = row0 + w * 16 + (lane >> 2);
    const int r1 = r0 + 8;
    int g0 = 0, g1 = 0;
    if (POOL) {
        g0 = (r0 < N_NODES) ? batch[r0] : 0;
        g1 = (r1 < N_NODES) ? batch[r1] : 0;
    }
#pragma unroll
    for (int t = 0; t < 16; t++) {
        int col = t * 8 + (lane & 3) * 2;
        float bv0 = bias[col], bv1 = bias[col + 1];
        float v00 = c[t][0] + bv0, v01 = c[t][1] + bv1;
        float v10 = c[t][2] + bv0, v11 = c[t][3] + bv1;
        if (!POOL) {
            v00 = fmaxf(v00, 0.f); v01 = fmaxf(v01, 0.f);
            v10 = fmaxf(v10, 0.f); v11 = fmaxf(v11, 0.f);
            unsigned h0v, l0v, h1v, l1v;
            split2(v00, v01, h0v, l0v);
            split2(v10, v11, h1v, l1v);
            *(unsigned*)(g_cath + (size_t)r0 * 256 + 128 + col) = h0v;
            *(unsigned*)(g_catl + (size_t)r0 * 256 + 128 + col) = l0v;
            *(unsigned*)(g_cath + (size_t)r1 * 256 + 128 + col) = h1v;
            *(unsigned*)(g_catl + (size_t)r1 * 256 + 128 + col) = l1v;
        } else {
            if (r0 < N_NODES) {
                atomicAdd(&g_pooled[(size_t)g0 * HID + col], v00);
                atomicAdd(&g_pooled[(size_t)g0 * HID + col + 1], v01);
            }
            if (r1 < N_NODES) {
                atomicAdd(&g_pooled[(size_t)g1 * HID + col], v10);
                atomicAdd(&g_pooled[(size_t)g1 * HID + col + 1], v11);
            }
        }
    }
}

// ---------------- final: mean pool -> linear -> sigmoid ----------------
__global__ void k_final(const float* __restrict__ Wlin, const float* __restrict__ blin,
                        float* __restrict__ out) {
    int g = blockIdx.x;
    int t = threadIdx.x;              // 128
    float cnt = fmaxf((float)g_cnt[g], 1.0f);
    float v = g_pooled[(size_t)g * HID + t] * (1.0f / cnt) * Wlin[t];
#pragma unroll
    for (int off = 16; off > 0; off >>= 1)
        v += __shfl_xor_sync(0xffffffffu, v, off);
    __shared__ float ws[4];
    if ((t & 31) == 0) ws[t >> 5] = v;
    __syncthreads();
    if (t == 0) {
        float s = ws[0] + ws[1] + ws[2] + ws[3] + blin[0];
        out[g] = 1.0f / (1.0f + expf(-s));
    }
}

// ---------------- launch ----------------
extern "C" void kernel_launch(void* const* d_in, const int* in_sizes, int n_in,
                              void* d_out, int out_size) {
    const float* x      = (const float*)d_in[0];
    const int*   ei     = (const int*)d_in[1];
    const int*   batch  = (const int*)d_in[2];
    const float* Wrel0  = (const float*)d_in[3];
    const float* brel0  = (const float*)d_in[4];
    const float* Wroot0 = (const float*)d_in[5];
    const float* Wrel1  = (const float*)d_in[6];
    const float* brel1  = (const float*)d_in[7];
    const float* Wroot1 = (const float*)d_in[8];
    const float* Wrel2  = (const float*)d_in[9];
    const float* brel2  = (const float*)d_in[10];
    const float* Wroot2 = (const float*)d_in[11];
    const float* Wlin   = (const float*)d_in[12];
    const float* blin   = (const float*)d_in[13];
    float* out = (float*)d_out;

    k_zero<<<(NUM_GRAPHS * HID + 255) / 256, 256>>>();
    k_hist<<<(N_EDGES + 255) / 256, 256>>>(ei);
    k_wconv<<<(2 * 256 * HID + 255) / 256, 256>>>(Wrel1, Wroot1, Wrel2, Wroot2);
    k_scan<<<1, 1024>>>();
    k_scatter<<<(N_EDGES + 255) / 256, 256>>>(ei);
    k_cnt<<<(N_NODES + 255) / 256, 256>>>(batch);

    // layer 0
    k_agg0<<<(N_NODES + 255) / 256, 256>>>(x);
    k_h0<<<N_NODES, HID>>>(x, Wrel0, brel0, Wroot0);

    // layer 1
    k_gather<<<(N_NODES * 32 + 255) / 256, 256>>>();
    k_gemm<0><<<N_PAD / 64, 128>>>(brel1, batch);

    // layer 2 (+ fused pooling accumulate)
    k_gather<<<(N_NODES * 32 + 255) / 256, 256>>>();
    k_gemm<1><<<N_PAD / 64, 128>>>(brel2, batch);

    // head
    k_final<<<NUM_GRAPHS, HID>>>(Wlin, blin, out);
}

// round 8
// speedup vs baseline: 1.9109x; 1.9109x over previous
#include <cuda_runtime.h>
#include <cuda_fp16.h>
#include <math.h>

#define N_NODES 50000
#define N_PAD   50048           // 391 * 128
#define N_EDGES 640000
#define IN_DIM 5
#define HID 128
#define NUM_GRAPHS 512
#define NB 196                  // scan blocks: 196*256 >= N_NODES

// ---------------- device scratch (static, no allocation) ----------------
// cat[n][0:128] = agg, cat[n][128:256] = h ; hi/lo fp16 split (hi+lo ~= fp32)
__device__ __align__(16) __half g_cath[(size_t)N_PAD * 256];
__device__ __align__(16) __half g_catl[(size_t)N_PAD * 256];
__device__ __align__(16) __half g_W1hi[256 * HID], g_W1lo[256 * HID];
__device__ __align__(16) __half g_W2hi[256 * HID], g_W2lo[256 * HID];
__device__ __align__(16) float  g_agg0[N_NODES * IN_DIM];
__device__ float g_pooled[NUM_GRAPHS * HID];
__device__ int   g_deg   [N_NODES];
__device__ int   g_rowptr[N_NODES + 1];
__device__ int   g_cursor[N_NODES];
__device__ int   g_csr_src[N_EDGES];
__device__ int   g_cnt   [NUM_GRAPHS];
__device__ int   g_blksum[NB];
__device__ int   g_blkoff[NB];

// split helpers
__device__ __forceinline__ void split2(float v0, float v1, unsigned& hi, unsigned& lo) {
    __half2 h = __floats2half2_rn(v0, v1);
    float2 hf = __half22float2(h);
    __half2 l = __floats2half2_rn(v0 - hf.x, v1 - hf.y);
    hi = *(unsigned*)&h;
    lo = *(unsigned*)&l;
}

// ---------------- zero init (+ zero pad rows of cat hi/lo) ----------------
__global__ void k_zero() {
    int i = blockIdx.x * blockDim.x + threadIdx.x;
    if (i < N_NODES) g_deg[i] = 0;
    if (i < NUM_GRAPHS * HID) g_pooled[i] = 0.0f;
    if (i < NUM_GRAPHS) g_cnt[i] = 0;
    if (i < (N_PAD - N_NODES) * 256 / 2) {    // 48 pad rows, as uint
        ((unsigned*)(g_cath + (size_t)N_NODES * 256))[i] = 0u;
        ((unsigned*)(g_catl + (size_t)N_NODES * 256))[i] = 0u;
    }
}

// ---------------- CSR build ----------------
__global__ void k_hist(const int* __restrict__ ei) {
    int e = blockIdx.x * blockDim.x + threadIdx.x;
    if (e < N_EDGES) atomicAdd(&g_deg[ei[N_EDGES + e]], 1);
}

// hierarchical exclusive scan of g_deg -> g_rowptr/g_cursor
__global__ void k_scanA() {
    __shared__ int red[256];
    int t = blockIdx.x * 256 + threadIdx.x;
    int d = (t < N_NODES) ? g_deg[t] : 0;
    red[threadIdx.x] = d;
    __syncthreads();
#pragma unroll
    for (int off = 128; off > 0; off >>= 1) {
        if (threadIdx.x < off) red[threadIdx.x] += red[threadIdx.x + off];
        __syncthreads();
    }
    if (threadIdx.x == 0) g_blksum[blockIdx.x] = red[0];
}

__global__ void k_scanB() {        // 1 block, 256 threads, scans NB=196 sums
    __shared__ int s[256];
    int t = threadIdx.x;
    int v = (t < NB) ? g_blksum[t] : 0;
    s[t] = v;
    __syncthreads();
#pragma unroll
    for (int off = 1; off < 256; off <<= 1) {
        int u = (t >= off) ? s[t - off] : 0;
        __syncthreads();
        s[t] += u;
        __syncthreads();
    }
    if (t < NB) g_blkoff[t] = s[t] - v;        // exclusive prefix
    if (t == NB - 1) g_rowptr[N_NODES] = s[t]; // total
}

__global__ void k_scanC() {
    __shared__ int s[256];
    int t = blockIdx.x * 256 + threadIdx.x;
    int tt = threadIdx.x;
    int d = (t < N_NODES) ? g_deg[t] : 0;
    s[tt] = d;
    __syncthreads();
#pragma unroll
    for (int off = 1; off < 256; off <<= 1) {
        int u = (tt >= off) ? s[tt - off] : 0;
        __syncthreads();
        s[tt] += u;
        __syncthreads();
    }
    int excl = s[tt] - d + g_blkoff[blockIdx.x];
    if (t < N_NODES) {
        g_rowptr[t] = excl;
        g_cursor[t] = excl;
    }
}

__global__ void k_scatter(const int* __restrict__ ei) {
    int e = blockIdx.x * blockDim.x + threadIdx.x;
    if (e < N_EDGES) {
        int d = ei[N_EDGES + e];
        int p = atomicAdd(&g_cursor[d], 1);
        g_csr_src[p] = ei[e];
    }
}

__global__ void k_cnt(const int* __restrict__ batch) {
    int i = blockIdx.x * blockDim.x + threadIdx.x;
    if (i < N_NODES) atomicAdd(&g_cnt[batch[i]], 1);
}

// ---------------- weight conversion: stacked [Wrel; Wroot] -> fp16 hi/lo ----
__global__ void k_wconv(const float* __restrict__ Wrel1, const float* __restrict__ Wroot1,
                        const float* __restrict__ Wrel2, const float* __restrict__ Wroot2) {
    int i = blockIdx.x * blockDim.x + threadIdx.x;   // 2 * 256 * 128
    if (i >= 2 * 256 * HID) return;
    int layer = i >> 15;
    int j = i & 32767;
    int r = j >> 7, c = j & 127;
    const float* Wr = layer ? Wrel2 : Wrel1;
    const float* Wo = layer ? Wroot2 : Wroot1;
    float v = (r < 128) ? Wr[r * HID + c] : Wo[(r - 128) * HID + c];
    __half hi = __float2half_rn(v);
    __half lo = __float2half_rn(v - __half2float(hi));
    if (layer) { g_W2hi[j] = hi; g_W2lo[j] = lo; }
    else       { g_W1hi[j] = hi; g_W1lo[j] = lo; }
}

// ---------------- layer 0 (IN_DIM = 5) ----------------
__global__ void k_agg0(const float* __restrict__ x) {
    int n = blockIdx.x * blockDim.x + threadIdx.x;
    if (n >= N_NODES) return;
    float s0 = 0.f, s1 = 0.f, s2 = 0.f, s3 = 0.f, s4 = 0.f;
    int beg = g_rowptr[n], end = g_rowptr[n + 1];
    for (int j = beg; j < end; j++) {
        const float* xr = x + (size_t)g_csr_src[j] * IN_DIM;
        s0 += xr[0]; s1 += xr[1]; s2 += xr[2]; s3 += xr[3]; s4 += xr[4];
    }
    float* o = g_agg0 + (size_t)n * IN_DIM;
    o[0] = s0; o[1] = s1; o[2] = s2; o[3] = s3; o[4] = s4;
}

__global__ void k_h0(const float* __restrict__ x,
                     const float* __restrict__ Wrel, const float* __restrict__ brel,
                     const float* __restrict__ Wroot) {
    __shared__ float sa[IN_DIM], sx[IN_DIM];
    int n = blockIdx.x;
    int c = threadIdx.x;              // 128 threads
    if (c < IN_DIM) {
        sa[c] = g_agg0[(size_t)n * IN_DIM + c];
        sx[c] = x[(size_t)n * IN_DIM + c];
    }
    __syncthreads();
    float v = brel[c];
#pragma unroll
    for (int k = 0; k < IN_DIM; k++) {
        v = fmaf(sa[k], Wrel[k * HID + c], v);
        v = fmaf(sx[k], Wroot[k * HID + c], v);
    }
    v = fmaxf(v, 0.0f);
    __half hi = __float2half_rn(v);
    __half lo = __float2half_rn(v - __half2float(hi));
    g_cath[(size_t)n * 256 + 128 + c] = hi;
    g_catl[(size_t)n * 256 + 128 + c] = lo;
}

// ---------------- edge aggregation, warp per node ----------------
__global__ void k_gather() {
    int node = (blockIdx.x * blockDim.x + threadIdx.x) >> 5;
    int lane = threadIdx.x & 31;
    if (node >= N_NODES) return;
    float a0 = 0.f, a1 = 0.f, a2 = 0.f, a3 = 0.f;
    int beg = g_rowptr[node], end = g_rowptr[node + 1];
    int j = beg;
    for (; j + 1 < end; j += 2) {
        int s0 = g_csr_src[j], s1 = g_csr_src[j + 1];
        uint2 p0 = __ldg((const uint2*)(g_cath + (size_t)s0 * 256 + 128) + lane);
        uint2 p1 = __ldg((const uint2*)(g_cath + (size_t)s1 * 256 + 128) + lane);
        float2 f0 = __half22float2(*(__half2*)&p0.x);
        float2 f1 = __half22float2(*(__half2*)&p0.y);
        float2 q0 = __half22float2(*(__half2*)&p1.x);
        float2 q1 = __half22float2(*(__half2*)&p1.y);
        a0 += f0.x + q0.x; a1 += f0.y + q0.y;
        a2 += f1.x + q1.x; a3 += f1.y + q1.y;
    }
    if (j < end) {
        int s0 = g_csr_src[j];
        uint2 p0 = __ldg((const uint2*)(g_cath + (size_t)s0 * 256 + 128) + lane);
        float2 f0 = __half22float2(*(__half2*)&p0.x);
        float2 f1 = __half22float2(*(__half2*)&p0.y);
        a0 += f0.x; a1 += f0.y; a2 += f1.x; a3 += f1.y;
    }
    unsigned h01, l01, h23, l23;
    split2(a0, a1, h01, l01);
    split2(a2, a3, h23, l23);
    *((uint2*)(g_cath + (size_t)node * 256) + lane) = make_uint2(h01, h23);
    *((uint2*)(g_catl + (size_t)node * 256) + lane) = make_uint2(l01, l23);
}

// ---------------- split-fp16 tensor-core GEMM -----------------
// D = Ah*Wh + Ah*Wl + Al*Wh  (fp32 accumulate) ~ fp32-precision GEMM
__device__ __forceinline__ void mma16816(float* c, const unsigned* a,
                                         unsigned b0, unsigned b1) {
    asm volatile("mma.sync.aligned.m16n8k16.row.col.f32.f16.f16.f32 "
                 "{%0,%1,%2,%3}, {%4,%5,%6,%7}, {%8,%9}, {%0,%1,%2,%3};"
                 : "+f"(c[0]), "+f"(c[1]), "+f"(c[2]), "+f"(c[3])
                 : "r"(a[0]), "r"(a[1]), "r"(a[2]), "r"(a[3]), "r"(b0), "r"(b1));
}

#define LDMX4(dst, ptr)                                                          \
    { unsigned _ad = (unsigned)__cvta_generic_to_shared(ptr);                    \
      asm volatile("ldmatrix.sync.aligned.m8n8.x4.shared.b16 {%0,%1,%2,%3}, [%4];" \
                   : "=r"(dst[0]), "=r"(dst[1]), "=r"(dst[2]), "=r"(dst[3]) : "r"(_ad)); }
#define LDMX4T(dst, ptr)                                                         \
    { unsigned _ad = (unsigned)__cvta_generic_to_shared(ptr);                    \
      asm volatile("ldmatrix.sync.aligned.m8n8.x4.trans.shared.b16 {%0,%1,%2,%3}, [%4];" \
                   : "=r"(dst[0]), "=r"(dst[1]), "=r"(dst[2]), "=r"(dst[3]) : "r"(_ad)); }

// 128-row tile, 256 threads (8 warps x 16 rows).
// POOL==0: weights W1, relu, write h-slot hi/lo. POOL==1: weights W2, pool.
template <int POOL>
__global__ __launch_bounds__(256, 2)
void k_gemm(const float* __restrict__ bias, const int* __restrict__ batch) {
    __shared__ __half Ahs[128][24], Als[128][24];   // 128 rows x 16 k (+8 pad)
    __shared__ __half Whs[16][136], Wls[16][136];   // 16 k x 128 n (+8 pad)

    const __half* __restrict__ WH = POOL ? g_W2hi : g_W1hi;
    const __half* __restrict__ WL = POOL ? g_W2lo : g_W1lo;

    const int tid = threadIdx.x;
    const int lane = tid & 31;
    const int w = tid >> 5;           // 8 warps, warp w -> rows [w*16, w*16+16)
    const int row0 = blockIdx.x * 128;

    float c[16][4];
#pragma unroll
    for (int t = 0; t < 16; t++)
#pragma unroll
        for (int q = 0; q < 4; q++) c[t][q] = 0.0f;

    const int a_row = w * 16 + (lane & 15);
    const int a_co = (lane >> 4) << 3;
    const int b_kr = (lane & 7) + (((lane >> 3) & 1) << 3);
    const int b_no = (lane >> 4) << 3;

    for (int kc = 0; kc < 16; kc++) {
        int k0 = kc * 16;
        __syncthreads();
        // A chunk: 128 rows x 16 halfs, hi & lo (1 uint4 each per thread)
        {
            int r = tid >> 1, seg = tid & 1;
            *(uint4*)&Ahs[r][seg * 8] =
                *(const uint4*)(g_cath + (size_t)(row0 + r) * 256 + k0 + seg * 8);
            *(uint4*)&Als[r][seg * 8] =
                *(const uint4*)(g_catl + (size_t)(row0 + r) * 256 + k0 + seg * 8);
        }
        // W chunk: 16 x 128, hi & lo (1 uint4 each per thread)
        {
            int r = tid >> 4, seg = tid & 15;
            *(uint4*)&Whs[r][seg * 8] = *(const uint4*)(WH + (size_t)(k0 + r) * HID + seg * 8);
            *(uint4*)&Wls[r][seg * 8] = *(const uint4*)(WL + (size_t)(k0 + r) * HID + seg * 8);
        }
        __syncthreads();

        unsigned ah[4], al[4];
        LDMX4(ah, &Ahs[a_row][a_co]);
        LDMX4(al, &Als[a_row][a_co]);
#pragma unroll
        for (int t = 0; t < 8; t++) {
            unsigned bh[4], bl[4];
            LDMX4T(bh, &Whs[b_kr][t * 16 + b_no]);
            LDMX4T(bl, &Wls[b_kr][t * 16 + b_no]);
            mma16816(c[2 * t],     ah, bh[0], bh[1]);
            mma16816(c[2 * t],     ah, bl[0], bl[1]);
            mma16816(c[2 * t],     al, bh[0], bh[1]);
            mma16816(c[2 * t + 1], ah, bh[2], bh[3]);
            mma16816(c[2 * t + 1], ah, bl[2], bl[3]);
            mma16816(c[2 * t + 1], al, bh[2], bh[3]);
        }
    }

    // epilogue
    const int r0 = row0 + w * 16 + (lane >> 2);
    const int r1 = r0 + 8;
    int g0 = 0, g1 = 0;
    if (POOL) {
        g0 = (r0 < N_NODES) ? batch[r0] : 0;
        g1 = (r1 < N_NODES) ? batch[r1] : 0;
    }
#pragma unroll
    for (int t = 0; t < 16; t++) {
        int col = t * 8 + (lane & 3) * 2;
        float bv0 = bias[col], bv1 = bias[col + 1];
        float v00 = c[t][0] + bv0, v01 = c[t][1] + bv1;
        float v10 = c[t][2] + bv0, v11 = c[t][3] + bv1;
        if (!POOL) {
            v00 = fmaxf(v00, 0.f); v01 = fmaxf(v01, 0.f);
            v10 = fmaxf(v10, 0.f); v11 = fmaxf(v11, 0.f);
            unsigned h0v, l0v, h1v, l1v;
            split2(v00, v01, h0v, l0v);
            split2(v10, v11, h1v, l1v);
            *(unsigned*)(g_cath + (size_t)r0 * 256 + 128 + col) = h0v;
            *(unsigned*)(g_catl + (size_t)r0 * 256 + 128 + col) = l0v;
            *(unsigned*)(g_cath + (size_t)r1 * 256 + 128 + col) = h1v;
            *(unsigned*)(g_catl + (size_t)r1 * 256 + 128 + col) = l1v;
        } else {
            if (r0 < N_NODES) {
                atomicAdd(&g_pooled[(size_t)g0 * HID + col], v00);
                atomicAdd(&g_pooled[(size_t)g0 * HID + col + 1], v01);
            }
            if (r1 < N_NODES) {
                atomicAdd(&g_pooled[(size_t)g1 * HID + col], v10);
                atomicAdd(&g_pooled[(size_t)g1 * HID + col + 1], v11);
            }
        }
    }
}

// ---------------- final: mean pool -> linear -> sigmoid ----------------
__global__ void k_final(const float* __restrict__ Wlin, const float* __restrict__ blin,
                        float* __restrict__ out) {
    int g = blockIdx.x;
    int t = threadIdx.x;              // 128
    float cnt = fmaxf((float)g_cnt[g], 1.0f);
    float v = g_pooled[(size_t)g * HID + t] * (1.0f / cnt) * Wlin[t];
#pragma unroll
    for (int off = 16; off > 0; off >>= 1)
        v += __shfl_xor_sync(0xffffffffu, v, off);
    __shared__ float ws[4];
    if ((t & 31) == 0) ws[t >> 5] = v;
    __syncthreads();
    if (t == 0) {
        float s = ws[0] + ws[1] + ws[2] + ws[3] + blin[0];
        out[g] = 1.0f / (1.0f + expf(-s));
    }
}

// ---------------- launch ----------------
extern "C" void kernel_launch(void* const* d_in, const int* in_sizes, int n_in,
                              void* d_out, int out_size) {
    const float* x      = (const float*)d_in[0];
    const int*   ei     = (const int*)d_in[1];
    const int*   batch  = (const int*)d_in[2];
    const float* Wrel0  = (const float*)d_in[3];
    const float* brel0  = (const float*)d_in[4];
    const float* Wroot0 = (const float*)d_in[5];
    const float* Wrel1  = (const float*)d_in[6];
    const float* brel1  = (const float*)d_in[7];
    const float* Wroot1 = (const float*)d_in[8];
    const float* Wrel2  = (const float*)d_in[9];
    const float* brel2  = (const float*)d_in[10];
    const float* Wroot2 = (const float*)d_in[11];
    const float* Wlin   = (const float*)d_in[12];
    const float* blin   = (const float*)d_in[13];
    float* out = (float*)d_out;

    k_zero<<<(NUM_GRAPHS * HID + 255) / 256, 256>>>();
    k_hist<<<(N_EDGES + 255) / 256, 256>>>(ei);
    k_wconv<<<(2 * 256 * HID + 255) / 256, 256>>>(Wrel1, Wroot1, Wrel2, Wroot2);
    k_scanA<<<NB, 256>>>();
    k_scanB<<<1, 256>>>();
    k_scanC<<<NB, 256>>>();
    k_scatter<<<(N_EDGES + 255) / 256, 256>>>(ei);
    k_cnt<<<(N_NODES + 255) / 256, 256>>>(batch);

    // layer 0
    k_agg0<<<(N_NODES + 255) / 256, 256>>>(x);
    k_h0<<<N_NODES, HID>>>(x, Wrel0, brel0, Wroot0);

    // layer 1
    k_gather<<<(N_NODES * 32 + 255) / 256, 256>>>();
    k_gemm<0><<<N_PAD / 128, 256>>>(brel1, batch);

    // layer 2 (+ fused pooling accumulate)
    k_gather<<<(N_NODES * 32 + 255) / 256, 256>>>();
    k_gemm<1><<<N_PAD / 128, 256>>>(brel2, batch);

    // head
    k_final<<<NUM_GRAPHS, HID>>>(Wlin, blin, out);
}

// round 9
// speedup vs baseline: 2.3715x; 1.2410x over previous
#include <cuda_runtime.h>
#include <cuda_fp16.h>
#include <math.h>

#define N_NODES 50000
#define N_PAD   50048           // 391 * 128
#define N_EDGES 640000
#define IN_DIM 5
#define HID 128
#define NUM_GRAPHS 512
#define NB 196                  // scan blocks: 196*256 >= N_NODES

// ---------------- device scratch (static, no allocation) ----------------
// cat[n][0:128] = agg, cat[n][128:256] = h ; hi/lo fp16 split (hi+lo ~= fp32)
__device__ __align__(16) __half g_cath[(size_t)N_PAD * 256];
__device__ __align__(16) __half g_catl[(size_t)N_PAD * 256];
__device__ __align__(16) __half g_W1hi[256 * HID], g_W1lo[256 * HID];
__device__ __align__(16) __half g_W2hi[256 * HID], g_W2lo[256 * HID];
__device__ float g_pooled[NUM_GRAPHS * HID];
__device__ int   g_deg   [N_NODES];
__device__ int   g_rowptr[N_NODES + 1];
__device__ int   g_cursor[N_NODES];
__device__ int   g_csr_src[N_EDGES];
__device__ int   g_cnt   [NUM_GRAPHS];
__device__ int   g_blksum[NB];
__device__ int   g_blkoff[NB];

// split helpers
__device__ __forceinline__ void split2(float v0, float v1, unsigned& hi, unsigned& lo) {
    __half2 h = __floats2half2_rn(v0, v1);
    float2 hf = __half22float2(h);
    __half2 l = __floats2half2_rn(v0 - hf.x, v1 - hf.y);
    hi = *(unsigned*)&h;
    lo = *(unsigned*)&l;
}

// ---------------- zero init (+ zero pad rows of cat hi/lo) ----------------
__global__ void k_zero() {
    int i = blockIdx.x * blockDim.x + threadIdx.x;
    if (i < N_NODES) g_deg[i] = 0;
    if (i < NUM_GRAPHS * HID) g_pooled[i] = 0.0f;
    if (i < NUM_GRAPHS) g_cnt[i] = 0;
    if (i < (N_PAD - N_NODES) * 256 / 2) {    // 48 pad rows, as uint
        ((unsigned*)(g_cath + (size_t)N_NODES * 256))[i] = 0u;
        ((unsigned*)(g_catl + (size_t)N_NODES * 256))[i] = 0u;
    }
}

// ---------------- CSR build: histogram + per-graph node counts ----------------
__global__ void k_histcnt(const int* __restrict__ ei, const int* __restrict__ batch) {
    int e = blockIdx.x * blockDim.x + threadIdx.x;
    if (e < N_EDGES) atomicAdd(&g_deg[ei[N_EDGES + e]], 1);
    if (e < N_NODES) atomicAdd(&g_cnt[batch[e]], 1);
}

// hierarchical exclusive scan of g_deg -> g_rowptr/g_cursor
__global__ void k_scanA() {
    __shared__ int red[256];
    int t = blockIdx.x * 256 + threadIdx.x;
    int d = (t < N_NODES) ? g_deg[t] : 0;
    red[threadIdx.x] = d;
    __syncthreads();
#pragma unroll
    for (int off = 128; off > 0; off >>= 1) {
        if (threadIdx.x < off) red[threadIdx.x] += red[threadIdx.x + off];
        __syncthreads();
    }
    if (threadIdx.x == 0) g_blksum[blockIdx.x] = red[0];
}

__global__ void k_scanB() {        // 1 block, 256 threads, scans NB=196 sums
    __shared__ int s[256];
    int t = threadIdx.x;
    int v = (t < NB) ? g_blksum[t] : 0;
    s[t] = v;
    __syncthreads();
#pragma unroll
    for (int off = 1; off < 256; off <<= 1) {
        int u = (t >= off) ? s[t - off] : 0;
        __syncthreads();
        s[t] += u;
        __syncthreads();
    }
    if (t < NB) g_blkoff[t] = s[t] - v;        // exclusive prefix
    if (t == NB - 1) g_rowptr[N_NODES] = s[t]; // total
}

__global__ void k_scanC() {
    __shared__ int s[256];
    int t = blockIdx.x * 256 + threadIdx.x;
    int tt = threadIdx.x;
    int d = (t < N_NODES) ? g_deg[t] : 0;
    s[tt] = d;
    __syncthreads();
#pragma unroll
    for (int off = 1; off < 256; off <<= 1) {
        int u = (tt >= off) ? s[tt - off] : 0;
        __syncthreads();
        s[tt] += u;
        __syncthreads();
    }
    int excl = s[tt] - d + g_blkoff[blockIdx.x];
    if (t < N_NODES) {
        g_rowptr[t] = excl;
        g_cursor[t] = excl;
    }
}

__global__ void k_scatter(const int* __restrict__ ei) {
    int e = blockIdx.x * blockDim.x + threadIdx.x;
    if (e < N_EDGES) {
        int d = ei[N_EDGES + e];
        int p = atomicAdd(&g_cursor[d], 1);
        g_csr_src[p] = ei[e];
    }
}

// ---------------- weight conversion: stacked [Wrel; Wroot] -> fp16 hi/lo ----
__global__ void k_wconv(const float* __restrict__ Wrel1, const float* __restrict__ Wroot1,
                        const float* __restrict__ Wrel2, const float* __restrict__ Wroot2) {
    int i = blockIdx.x * blockDim.x + threadIdx.x;   // 2 * 256 * 128
    if (i >= 2 * 256 * HID) return;
    int layer = i >> 15;
    int j = i & 32767;
    int r = j >> 7, c = j & 127;
    const float* Wr = layer ? Wrel2 : Wrel1;
    const float* Wo = layer ? Wroot2 : Wroot1;
    float v = (r < 128) ? Wr[r * HID + c] : Wo[(r - 128) * HID + c];
    __half hi = __float2half_rn(v);
    __half lo = __float2half_rn(v - __half2float(hi));
    if (layer) { g_W2hi[j] = hi; g_W2lo[j] = lo; }
    else       { g_W1hi[j] = hi; g_W1lo[j] = lo; }
}

// ---------------- layer 0 fused: agg + linear + relu, warp per node --------
// edge-parallel lanes -> 5-dim partial sums -> shfl reduce -> 4 cols per lane
__global__ __launch_bounds__(256)
void k_l0(const float* __restrict__ x,
          const float* __restrict__ Wrel, const float* __restrict__ brel,
          const float* __restrict__ Wroot) {
    int node = (blockIdx.x * blockDim.x + threadIdx.x) >> 5;
    int lane = threadIdx.x & 31;
    if (node >= N_NODES) return;

    float s[IN_DIM];
#pragma unroll
    for (int k = 0; k < IN_DIM; k++) s[k] = 0.0f;

    int beg = g_rowptr[node], end = g_rowptr[node + 1];
    for (int j = beg + lane; j < end; j += 32) {
        const float* xr = x + (size_t)g_csr_src[j] * IN_DIM;
#pragma unroll
        for (int k = 0; k < IN_DIM; k++) s[k] += __ldg(xr + k);
    }
#pragma unroll
    for (int k = 0; k < IN_DIM; k++) {
#pragma unroll
        for (int off = 16; off > 0; off >>= 1)
            s[k] += __shfl_xor_sync(0xffffffffu, s[k], off);
    }

    float sx[IN_DIM];
#pragma unroll
    for (int k = 0; k < IN_DIM; k++) sx[k] = __ldg(&x[(size_t)node * IN_DIM + k]);

    int c0 = lane * 4;
    float4 v = *(const float4*)(brel + c0);
#pragma unroll
    for (int k = 0; k < IN_DIM; k++) {
        float4 wr = *(const float4*)(Wrel + k * HID + c0);
        float4 wo = *(const float4*)(Wroot + k * HID + c0);
        v.x = fmaf(s[k], wr.x, fmaf(sx[k], wo.x, v.x));
        v.y = fmaf(s[k], wr.y, fmaf(sx[k], wo.y, v.y));
        v.z = fmaf(s[k], wr.z, fmaf(sx[k], wo.z, v.z));
        v.w = fmaf(s[k], wr.w, fmaf(sx[k], wo.w, v.w));
    }
    v.x = fmaxf(v.x, 0.f); v.y = fmaxf(v.y, 0.f);
    v.z = fmaxf(v.z, 0.f); v.w = fmaxf(v.w, 0.f);

    unsigned h01, l01, h23, l23;
    split2(v.x, v.y, h01, l01);
    split2(v.z, v.w, h23, l23);
    *(uint2*)(g_cath + (size_t)node * 256 + 128 + c0) = make_uint2(h01, h23);
    *(uint2*)(g_catl + (size_t)node * 256 + 128 + c0) = make_uint2(l01, l23);
}

// ---------------- edge aggregation, warp per node ----------------
__global__ void k_gather() {
    int node = (blockIdx.x * blockDim.x + threadIdx.x) >> 5;
    int lane = threadIdx.x & 31;
    if (node >= N_NODES) return;
    float a0 = 0.f, a1 = 0.f, a2 = 0.f, a3 = 0.f;
    int beg = g_rowptr[node], end = g_rowptr[node + 1];
    int j = beg;
    for (; j + 1 < end; j += 2) {
        int s0 = g_csr_src[j], s1 = g_csr_src[j + 1];
        uint2 p0 = __ldg((const uint2*)(g_cath + (size_t)s0 * 256 + 128) + lane);
        uint2 p1 = __ldg((const uint2*)(g_cath + (size_t)s1 * 256 + 128) + lane);
        float2 f0 = __half22float2(*(__half2*)&p0.x);
        float2 f1 = __half22float2(*(__half2*)&p0.y);
        float2 q0 = __half22float2(*(__half2*)&p1.x);
        float2 q1 = __half22float2(*(__half2*)&p1.y);
        a0 += f0.x + q0.x; a1 += f0.y + q0.y;
        a2 += f1.x + q1.x; a3 += f1.y + q1.y;
    }
    if (j < end) {
        int s0 = g_csr_src[j];
        uint2 p0 = __ldg((const uint2*)(g_cath + (size_t)s0 * 256 + 128) + lane);
        float2 f0 = __half22float2(*(__half2*)&p0.x);
        float2 f1 = __half22float2(*(__half2*)&p0.y);
        a0 += f0.x; a1 += f0.y; a2 += f1.x; a3 += f1.y;
    }
    unsigned h01, l01, h23, l23;
    split2(a0, a1, h01, l01);
    split2(a2, a3, h23, l23);
    *((uint2*)(g_cath + (size_t)node * 256) + lane) = make_uint2(h01, h23);
    *((uint2*)(g_catl + (size_t)node * 256) + lane) = make_uint2(l01, l23);
}

// ---------------- split-fp16 tensor-core GEMM -----------------
// D = Ah*Wh + Ah*Wl + Al*Wh  (fp32 accumulate) ~ fp32-precision GEMM
__device__ __forceinline__ void mma16816(float* c, const unsigned* a,
                                         unsigned b0, unsigned b1) {
    asm volatile("mma.sync.aligned.m16n8k16.row.col.f32.f16.f16.f32 "
                 "{%0,%1,%2,%3}, {%4,%5,%6,%7}, {%8,%9}, {%0,%1,%2,%3};"
                 : "+f"(c[0]), "+f"(c[1]), "+f"(c[2]), "+f"(c[3])
                 : "r"(a[0]), "r"(a[1]), "r"(a[2]), "r"(a[3]), "r"(b0), "r"(b1));
}

#define LDMX4(dst, ptr)                                                          \
    { unsigned _ad = (unsigned)__cvta_generic_to_shared(ptr);                    \
      asm volatile("ldmatrix.sync.aligned.m8n8.x4.shared.b16 {%0,%1,%2,%3}, [%4];" \
                   : "=r"(dst[0]), "=r"(dst[1]), "=r"(dst[2]), "=r"(dst[3]) : "r"(_ad)); }
#define LDMX4T(dst, ptr)                                                         \
    { unsigned _ad = (unsigned)__cvta_generic_to_shared(ptr);                    \
      asm volatile("ldmatrix.sync.aligned.m8n8.x4.trans.shared.b16 {%0,%1,%2,%3}, [%4];" \
                   : "=r"(dst[0]), "=r"(dst[1]), "=r"(dst[2]), "=r"(dst[3]) : "r"(_ad)); }

// 128x128 block tile, 256 threads. Warp grid 4x2: warp tile 32 rows x 64 cols.
// K-chunk 32 (8 chunks over K=256).
// POOL==0: weights W1, relu, write h-slot hi/lo. POOL==1: weights W2, pool.
template <int POOL>
__global__ __launch_bounds__(256, 2)
void k_gemm(const float* __restrict__ bias, const int* __restrict__ batch) {
    __shared__ __half Ahs[128][40], Als[128][40];   // 128 rows x 32 k (+8 pad)
    __shared__ __half Whs[32][136], Wls[32][136];   // 32 k x 128 n (+8 pad)

    const __half* __restrict__ WH = POOL ? g_W2hi : g_W1hi;
    const __half* __restrict__ WL = POOL ? g_W2lo : g_W1lo;

    const int tid = threadIdx.x;
    const int lane = tid & 31;
    const int w = tid >> 5;
    const int wr = w >> 1;            // 0..3 : rows wr*32 .. +32
    const int wc = w & 1;             // 0..1 : cols wc*64 .. +64
    const int row0 = blockIdx.x * 128;

    float c[2][8][4];                 // [rowfrag 16][coltile 8][4]
#pragma unroll
    for (int i = 0; i < 2; i++)
#pragma unroll
        for (int t = 0; t < 8; t++)
#pragma unroll
            for (int q = 0; q < 4; q++) c[i][t][q] = 0.0f;

    const int a_co = (lane >> 4) << 3;                     // 0 or 8
    const int b_kr = (lane & 7) + (((lane >> 3) & 1) << 3);
    const int b_no = (lane >> 4) << 3;

    for (int kc = 0; kc < 8; kc++) {
        int k0 = kc * 32;
        __syncthreads();
        // A chunk: 128 rows x 32 halfs, hi & lo: 512 uint4 each, 2/thread each
#pragma unroll
        for (int i = 0; i < 2; i++) {
            int idx = tid + i * 256;
            int r = idx >> 2, c4 = idx & 3;
            *(uint4*)&Ahs[r][c4 * 8] =
                *(const uint4*)(g_cath + (size_t)(row0 + r) * 256 + k0 + c4 * 8);
            *(uint4*)&Als[r][c4 * 8] =
                *(const uint4*)(g_catl + (size_t)(row0 + r) * 256 + k0 + c4 * 8);
        }
        // W chunk: 32 k x 128 n, hi & lo: 512 uint4 each, 2/thread each
#pragma unroll
        for (int i = 0; i < 2; i++) {
            int idx = tid + i * 256;
            int r = idx >> 4, seg = idx & 15;
            *(uint4*)&Whs[r][seg * 8] = *(const uint4*)(WH + (size_t)(k0 + r) * HID + seg * 8);
            *(uint4*)&Wls[r][seg * 8] = *(const uint4*)(WL + (size_t)(k0 + r) * HID + seg * 8);
        }
        __syncthreads();

#pragma unroll
        for (int kh = 0; kh < 32; kh += 16) {
            unsigned ah0[4], al0[4], ah1[4], al1[4];
            LDMX4(ah0, &Ahs[wr * 32 + (lane & 15)][kh + a_co]);
            LDMX4(al0, &Als[wr * 32 + (lane & 15)][kh + a_co]);
            LDMX4(ah1, &Ahs[wr * 32 + 16 + (lane & 15)][kh + a_co]);
            LDMX4(al1, &Als[wr * 32 + 16 + (lane & 15)][kh + a_co]);
#pragma unroll
            for (int t = 0; t < 4; t++) {
                unsigned bh[4], bl[4];
                LDMX4T(bh, &Whs[kh + b_kr][wc * 64 + t * 16 + b_no]);
                LDMX4T(bl, &Wls[kh + b_kr][wc * 64 + t * 16 + b_no]);
                mma16816(c[0][2 * t],     ah0, bh[0], bh[1]);
                mma16816(c[0][2 * t],     ah0, bl[0], bl[1]);
                mma16816(c[0][2 * t],     al0, bh[0], bh[1]);
                mma16816(c[0][2 * t + 1], ah0, bh[2], bh[3]);
                mma16816(c[0][2 * t + 1], ah0, bl[2], bl[3]);
                mma16816(c[0][2 * t + 1], al0, bh[2], bh[3]);
                mma16816(c[1][2 * t],     ah1, bh[0], bh[1]);
                mma16816(c[1][2 * t],     ah1, bl[0], bl[1]);
                mma16816(c[1][2 * t],     al1, bh[0], bh[1]);
                mma16816(c[1][2 * t + 1], ah1, bh[2], bh[3]);
                mma16816(c[1][2 * t + 1], ah1, bl[2], bl[3]);
                mma16816(c[1][2 * t + 1], al1, bh[2], bh[3]);
            }
        }
    }

    // epilogue: warp covers rows row0+wr*32+rf*16+{lane>>2, +8}, cols wc*64+t2*8+(lane&3)*2
#pragma unroll
    for (int rf = 0; rf < 2; rf++) {
        int r0 = row0 + wr * 32 + rf * 16 + (lane >> 2);
        int r1 = r0 + 8;
        int g0 = 0, g1 = 0;
        if (POOL) {
            g0 = (r0 < N_NODES) ? batch[r0] : 0;
            g1 = (r1 < N_NODES) ? batch[r1] : 0;
        }
#pragma unroll
        for (int t2 = 0; t2 < 8; t2++) {
            int col = wc * 64 + t2 * 8 + (lane & 3) * 2;
            float bv0 = bias[col], bv1 = bias[col + 1];
            float v00 = c[rf][t2][0] + bv0, v01 = c[rf][t2][1] + bv1;
            float v10 = c[rf][t2][2] + bv0, v11 = c[rf][t2][3] + bv1;
            if (!POOL) {
                v00 = fmaxf(v00, 0.f); v01 = fmaxf(v01, 0.f);
                v10 = fmaxf(v10, 0.f); v11 = fmaxf(v11, 0.f);
                unsigned h0v, l0v, h1v, l1v;
                split2(v00, v01, h0v, l0v);
                split2(v10, v11, h1v, l1v);
                *(unsigned*)(g_cath + (size_t)r0 * 256 + 128 + col) = h0v;
                *(unsigned*)(g_catl + (size_t)r0 * 256 + 128 + col) = l0v;
                *(unsigned*)(g_cath + (size_t)r1 * 256 + 128 + col) = h1v;
                *(unsigned*)(g_catl + (size_t)r1 * 256 + 128 + col) = l1v;
            } else {
                if (r0 < N_NODES) {
                    atomicAdd(&g_pooled[(size_t)g0 * HID + col], v00);
                    atomicAdd(&g_pooled[(size_t)g0 * HID + col + 1], v01);
                }
                if (r1 < N_NODES) {
                    atomicAdd(&g_pooled[(size_t)g1 * HID + col], v10);
                    atomicAdd(&g_pooled[(size_t)g1 * HID + col + 1], v11);
                }
            }
        }
    }
}

// ---------------- final: mean pool -> linear -> sigmoid ----------------
__global__ void k_final(const float* __restrict__ Wlin, const float* __restrict__ blin,
                        float* __restrict__ out) {
    int g = blockIdx.x;
    int t = threadIdx.x;              // 128
    float cnt = fmaxf((float)g_cnt[g], 1.0f);
    float v = g_pooled[(size_t)g * HID + t] * (1.0f / cnt) * Wlin[t];
#pragma unroll
    for (int off = 16; off > 0; off >>= 1)
        v += __shfl_xor_sync(0xffffffffu, v, off);
    __shared__ float ws[4];
    if ((t & 31) == 0) ws[t >> 5] = v;
    __syncthreads();
    if (t == 0) {
        float s = ws[0] + ws[1] + ws[2] + ws[3] + blin[0];
        out[g] = 1.0f / (1.0f + expf(-s));
    }
}

// ---------------- launch ----------------
extern "C" void kernel_launch(void* const* d_in, const int* in_sizes, int n_in,
                              void* d_out, int out_size) {
    const float* x      = (const float*)d_in[0];
    const int*   ei     = (const int*)d_in[1];
    const int*   batch  = (const int*)d_in[2];
    const float* Wrel0  = (const float*)d_in[3];
    const float* brel0  = (const float*)d_in[4];
    const float* Wroot0 = (const float*)d_in[5];
    const float* Wrel1  = (const float*)d_in[6];
    const float* brel1  = (const float*)d_in[7];
    const float* Wroot1 = (const float*)d_in[8];
    const float* Wrel2  = (const float*)d_in[9];
    const float* brel2  = (const float*)d_in[10];
    const float* Wroot2 = (const float*)d_in[11];
    const float* Wlin   = (const float*)d_in[12];
    const float* blin   = (const float*)d_in[13];
    float* out = (float*)d_out;

    k_zero<<<(NUM_GRAPHS * HID + 255) / 256, 256>>>();
    k_histcnt<<<(N_EDGES + 255) / 256, 256>>>(ei, batch);
    k_wconv<<<(2 * 256 * HID + 255) / 256, 256>>>(Wrel1, Wroot1, Wrel2, Wroot2);
    k_scanA<<<NB, 256>>>();
    k_scanB<<<1, 256>>>();
    k_scanC<<<NB, 256>>>();
    k_scatter<<<(N_EDGES + 255) / 256, 256>>>(ei);

    // layer 0 (fused agg + linear + relu)
    k_l0<<<(N_NODES * 32 + 255) / 256, 256>>>(x, Wrel0, brel0, Wroot0);

    // layer 1
    k_gather<<<(N_NODES * 32 + 255) / 256, 256>>>();
    k_gemm<0><<<N_PAD / 128, 256>>>(brel1, batch);

    // layer 2 (+ fused pooling accumulate)
    k_gather<<<(N_NODES * 32 + 255) / 256, 256>>>();
    k_gemm<1><<<N_PAD / 128, 256>>>(brel2, batch);

    // head
    k_final<<<NUM_GRAPHS, HID>>>(Wlin, blin, out);
}

// round 10
// speedup vs baseline: 2.4271x; 1.0234x over previous
#include <cuda_runtime.h>
#include <cuda_fp16.h>
#include <math.h>

#define N_NODES 50000
#define N_PAD   50048           // 391 * 128
#define N_EDGES 640000
#define IN_DIM 5
#define HID 128
#define NUM_GRAPHS 512
#define NB 196                  // scan blocks: 196*256 >= N_NODES

// ---------------- device scratch (static, no allocation) ----------------
// cat[n][0:128] = agg, cat[n][128:256] = h ; hi/lo fp16 split (hi+lo ~= fp32)
__device__ __align__(16) __half g_cath[(size_t)N_PAD * 256];
__device__ __align__(16) __half g_catl[(size_t)N_PAD * 256];
__device__ __align__(16) __half g_W1hi[256 * HID], g_W1lo[256 * HID];
__device__ __align__(16) __half g_W2hi[256 * HID], g_W2lo[256 * HID];
__device__ float g_pooled[NUM_GRAPHS * HID];
__device__ int   g_deg   [N_NODES];
__device__ int   g_rowptr[N_NODES + 1];
__device__ int   g_cursor[N_NODES];
__device__ int   g_csr_src[N_EDGES];
__device__ int   g_cnt   [NUM_GRAPHS];
__device__ int   g_blksum[NB];
__device__ int   g_blkoff[NB];

// split helpers
__device__ __forceinline__ void split2(float v0, float v1, unsigned& hi, unsigned& lo) {
    __half2 h = __floats2half2_rn(v0, v1);
    float2 hf = __half22float2(h);
    __half2 l = __floats2half2_rn(v0 - hf.x, v1 - hf.y);
    hi = *(unsigned*)&h;
    lo = *(unsigned*)&l;
}

// ---------------- zero init (+ zero pad rows of cat hi/lo) ----------------
__global__ void k_zero() {
    int i = blockIdx.x * blockDim.x + threadIdx.x;
    if (i < N_NODES) g_deg[i] = 0;
    if (i < NUM_GRAPHS * HID) g_pooled[i] = 0.0f;
    if (i < NUM_GRAPHS) g_cnt[i] = 0;
    if (i < (N_PAD - N_NODES) * 256 / 2) {    // 48 pad rows, as uint
        ((unsigned*)(g_cath + (size_t)N_NODES * 256))[i] = 0u;
        ((unsigned*)(g_catl + (size_t)N_NODES * 256))[i] = 0u;
    }
}

// ---------------- CSR build: histogram + per-graph node counts ----------------
__global__ void k_histcnt(const int* __restrict__ ei, const int* __restrict__ batch) {
    int e = blockIdx.x * blockDim.x + threadIdx.x;
    if (e < N_EDGES) atomicAdd(&g_deg[ei[N_EDGES + e]], 1);
    if (e < N_NODES) atomicAdd(&g_cnt[batch[e]], 1);
}

// hierarchical exclusive scan of g_deg -> g_rowptr/g_cursor
__global__ void k_scanA() {
    __shared__ int red[256];
    int t = blockIdx.x * 256 + threadIdx.x;
    int d = (t < N_NODES) ? g_deg[t] : 0;
    red[threadIdx.x] = d;
    __syncthreads();
#pragma unroll
    for (int off = 128; off > 0; off >>= 1) {
        if (threadIdx.x < off) red[threadIdx.x] += red[threadIdx.x + off];
        __syncthreads();
    }
    if (threadIdx.x == 0) g_blksum[blockIdx.x] = red[0];
}

__global__ void k_scanB() {        // 1 block, 256 threads, scans NB=196 sums
    __shared__ int s[256];
    int t = threadIdx.x;
    int v = (t < NB) ? g_blksum[t] : 0;
    s[t] = v;
    __syncthreads();
#pragma unroll
    for (int off = 1; off < 256; off <<= 1) {
        int u = (t >= off) ? s[t - off] : 0;
        __syncthreads();
        s[t] += u;
        __syncthreads();
    }
    if (t < NB) g_blkoff[t] = s[t] - v;        // exclusive prefix
    if (t == NB - 1) g_rowptr[N_NODES] = s[t]; // total
}

__global__ void k_scanC() {
    __shared__ int s[256];
    int t = blockIdx.x * 256 + threadIdx.x;
    int tt = threadIdx.x;
    int d = (t < N_NODES) ? g_deg[t] : 0;
    s[tt] = d;
    __syncthreads();
#pragma unroll
    for (int off = 1; off < 256; off <<= 1) {
        int u = (tt >= off) ? s[tt - off] : 0;
        __syncthreads();
        s[tt] += u;
        __syncthreads();
    }
    int excl = s[tt] - d + g_blkoff[blockIdx.x];
    if (t < N_NODES) {
        g_rowptr[t] = excl;
        g_cursor[t] = excl;
    }
}

__global__ void k_scatter(const int* __restrict__ ei) {
    int e = blockIdx.x * blockDim.x + threadIdx.x;
    if (e < N_EDGES) {
        int d = ei[N_EDGES + e];
        int p = atomicAdd(&g_cursor[d], 1);
        g_csr_src[p] = ei[e];
    }
}

// ---------------- weight conversion: stacked [Wrel; Wroot] -> fp16 hi/lo ----
__global__ void k_wconv(const float* __restrict__ Wrel1, const float* __restrict__ Wroot1,
                        const float* __restrict__ Wrel2, const float* __restrict__ Wroot2) {
    int i = blockIdx.x * blockDim.x + threadIdx.x;   // 2 * 256 * 128
    if (i >= 2 * 256 * HID) return;
    int layer = i >> 15;
    int j = i & 32767;
    int r = j >> 7, c = j & 127;
    const float* Wr = layer ? Wrel2 : Wrel1;
    const float* Wo = layer ? Wroot2 : Wroot1;
    float v = (r < 128) ? Wr[r * HID + c] : Wo[(r - 128) * HID + c];
    __half hi = __float2half_rn(v);
    __half lo = __float2half_rn(v - __half2float(hi));
    if (layer) { g_W2hi[j] = hi; g_W2lo[j] = lo; }
    else       { g_W1hi[j] = hi; g_W1lo[j] = lo; }
}

// ---------------- layer 0 fused: agg + linear + relu, warp per node --------
__global__ __launch_bounds__(256)
void k_l0(const float* __restrict__ x,
          const float* __restrict__ Wrel, const float* __restrict__ brel,
          const float* __restrict__ Wroot) {
    int node = (blockIdx.x * blockDim.x + threadIdx.x) >> 5;
    int lane = threadIdx.x & 31;
    if (node >= N_NODES) return;

    float s[IN_DIM];
#pragma unroll
    for (int k = 0; k < IN_DIM; k++) s[k] = 0.0f;

    int beg = g_rowptr[node], end = g_rowptr[node + 1];
    for (int j = beg + lane; j < end; j += 32) {
        const float* xr = x + (size_t)g_csr_src[j] * IN_DIM;
#pragma unroll
        for (int k = 0; k < IN_DIM; k++) s[k] += __ldg(xr + k);
    }
#pragma unroll
    for (int k = 0; k < IN_DIM; k++) {
#pragma unroll
        for (int off = 16; off > 0; off >>= 1)
            s[k] += __shfl_xor_sync(0xffffffffu, s[k], off);
    }

    float sx[IN_DIM];
#pragma unroll
    for (int k = 0; k < IN_DIM; k++) sx[k] = __ldg(&x[(size_t)node * IN_DIM + k]);

    int c0 = lane * 4;
    float4 v = *(const float4*)(brel + c0);
#pragma unroll
    for (int k = 0; k < IN_DIM; k++) {
        float4 wr = *(const float4*)(Wrel + k * HID + c0);
        float4 wo = *(const float4*)(Wroot + k * HID + c0);
        v.x = fmaf(s[k], wr.x, fmaf(sx[k], wo.x, v.x));
        v.y = fmaf(s[k], wr.y, fmaf(sx[k], wo.y, v.y));
        v.z = fmaf(s[k], wr.z, fmaf(sx[k], wo.z, v.z));
        v.w = fmaf(s[k], wr.w, fmaf(sx[k], wo.w, v.w));
    }
    v.x = fmaxf(v.x, 0.f); v.y = fmaxf(v.y, 0.f);
    v.z = fmaxf(v.z, 0.f); v.w = fmaxf(v.w, 0.f);

    unsigned h01, l01, h23, l23;
    split2(v.x, v.y, h01, l01);
    split2(v.z, v.w, h23, l23);
    *(uint2*)(g_cath + (size_t)node * 256 + 128 + c0) = make_uint2(h01, h23);
    *(uint2*)(g_catl + (size_t)node * 256 + 128 + c0) = make_uint2(l01, l23);
}

// ---------------- edge aggregation, warp per node (MLP=4) ----------------
__global__ void k_gather() {
    int node = (blockIdx.x * blockDim.x + threadIdx.x) >> 5;
    int lane = threadIdx.x & 31;
    if (node >= N_NODES) return;
    float a0 = 0.f, a1 = 0.f, a2 = 0.f, a3 = 0.f;
    int beg = g_rowptr[node], end = g_rowptr[node + 1];
    int j = beg;
    for (; j + 3 < end; j += 4) {
        int s0 = g_csr_src[j], s1 = g_csr_src[j + 1];
        int s2 = g_csr_src[j + 2], s3 = g_csr_src[j + 3];
        uint2 p0 = __ldg((const uint2*)(g_cath + (size_t)s0 * 256 + 128) + lane);
        uint2 p1 = __ldg((const uint2*)(g_cath + (size_t)s1 * 256 + 128) + lane);
        uint2 p2 = __ldg((const uint2*)(g_cath + (size_t)s2 * 256 + 128) + lane);
        uint2 p3 = __ldg((const uint2*)(g_cath + (size_t)s3 * 256 + 128) + lane);
        float2 f0 = __half22float2(*(__half2*)&p0.x);
        float2 f1 = __half22float2(*(__half2*)&p0.y);
        float2 g0 = __half22float2(*(__half2*)&p1.x);
        float2 g1 = __half22float2(*(__half2*)&p1.y);
        float2 q0 = __half22float2(*(__half2*)&p2.x);
        float2 q1 = __half22float2(*(__half2*)&p2.y);
        float2 r0 = __half22float2(*(__half2*)&p3.x);
        float2 r1 = __half22float2(*(__half2*)&p3.y);
        a0 += (f0.x + g0.x) + (q0.x + r0.x);
        a1 += (f0.y + g0.y) + (q0.y + r0.y);
        a2 += (f1.x + g1.x) + (q1.x + r1.x);
        a3 += (f1.y + g1.y) + (q1.y + r1.y);
    }
    for (; j < end; j++) {
        int s0 = g_csr_src[j];
        uint2 p0 = __ldg((const uint2*)(g_cath + (size_t)s0 * 256 + 128) + lane);
        float2 f0 = __half22float2(*(__half2*)&p0.x);
        float2 f1 = __half22float2(*(__half2*)&p0.y);
        a0 += f0.x; a1 += f0.y; a2 += f1.x; a3 += f1.y;
    }
    unsigned h01, l01, h23, l23;
    split2(a0, a1, h01, l01);
    split2(a2, a3, h23, l23);
    *((uint2*)(g_cath + (size_t)node * 256) + lane) = make_uint2(h01, h23);
    *((uint2*)(g_catl + (size_t)node * 256) + lane) = make_uint2(l01, l23);
}

// ---------------- split-fp16 tensor-core GEMM, cp.async pipelined ----------
// D = Ah*Wh + Ah*Wl + Al*Wh  (fp32 accumulate) ~ fp32-precision GEMM
__device__ __forceinline__ void mma16816(float* c, const unsigned* a,
                                         unsigned b0, unsigned b1) {
    asm volatile("mma.sync.aligned.m16n8k16.row.col.f32.f16.f16.f32 "
                 "{%0,%1,%2,%3}, {%4,%5,%6,%7}, {%8,%9}, {%0,%1,%2,%3};"
                 : "+f"(c[0]), "+f"(c[1]), "+f"(c[2]), "+f"(c[3])
                 : "r"(a[0]), "r"(a[1]), "r"(a[2]), "r"(a[3]), "r"(b0), "r"(b1));
}

#define LDMX4(dst, ptr)                                                          \
    { unsigned _ad = (unsigned)__cvta_generic_to_shared(ptr);                    \
      asm volatile("ldmatrix.sync.aligned.m8n8.x4.shared.b16 {%0,%1,%2,%3}, [%4];" \
                   : "=r"(dst[0]), "=r"(dst[1]), "=r"(dst[2]), "=r"(dst[3]) : "r"(_ad)); }
#define LDMX4T(dst, ptr)                                                         \
    { unsigned _ad = (unsigned)__cvta_generic_to_shared(ptr);                    \
      asm volatile("ldmatrix.sync.aligned.m8n8.x4.trans.shared.b16 {%0,%1,%2,%3}, [%4];" \
                   : "=r"(dst[0]), "=r"(dst[1]), "=r"(dst[2]), "=r"(dst[3]) : "r"(_ad)); }

__device__ __forceinline__ void cpa16(void* smem_dst, const void* gsrc) {
    unsigned d = (unsigned)__cvta_generic_to_shared(smem_dst);
    asm volatile("cp.async.cg.shared.global [%0], [%1], 16;" :: "r"(d), "l"(gsrc));
}
#define CP_COMMIT() asm volatile("cp.async.commit_group;")

// 128x128 block tile, 256 threads. Warp grid 4x2: warp tile 32 rows x 64 cols.
// K-chunk 16, 16 chunks over K=256, 2-stage cp.async double buffer.
// POOL==0: weights W1, relu, write h-slot hi/lo. POOL==1: weights W2, pool.
template <int POOL>
__global__ __launch_bounds__(256, 2)
void k_gemm(const float* __restrict__ bias, const int* __restrict__ batch) {
    __shared__ __half Ahs[2][128][24], Als[2][128][24];  // 128 x 16 (+8 pad)
    __shared__ __half Whs[2][16][136], Wls[2][16][136];  // 16 x 128 (+8 pad)

    const __half* __restrict__ WH = POOL ? g_W2hi : g_W1hi;
    const __half* __restrict__ WL = POOL ? g_W2lo : g_W1lo;

    const int tid = threadIdx.x;
    const int lane = tid & 31;
    const int w = tid >> 5;
    const int wr = w >> 1;            // 0..3 : rows wr*32 .. +32
    const int wc = w & 1;             // 0..1 : cols wc*64 .. +64
    const int row0 = blockIdx.x * 128;

    // per-thread cp.async coordinates (4 ops per chunk)
    const int a_r = tid >> 1, a_c = (tid & 1) * 8;        // A: 128 rows x 2 segs
    const int w_r = tid >> 4, w_c = (tid & 15) * 8;       // W: 16 rows x 16 segs

    float c[2][8][4];
#pragma unroll
    for (int i = 0; i < 2; i++)
#pragma unroll
        for (int t = 0; t < 8; t++)
#pragma unroll
            for (int q = 0; q < 4; q++) c[i][t][q] = 0.0f;

    const int a_co = (lane >> 4) << 3;                     // 0 or 8
    const int b_kr = (lane & 7) + (((lane >> 3) & 1) << 3);
    const int b_no = (lane >> 4) << 3;

    // prologue: load chunk 0 into buf 0
    {
        const int k0 = 0;
        cpa16(&Ahs[0][a_r][a_c], g_cath + (size_t)(row0 + a_r) * 256 + k0 + a_c);
        cpa16(&Als[0][a_r][a_c], g_catl + (size_t)(row0 + a_r) * 256 + k0 + a_c);
        cpa16(&Whs[0][w_r][w_c], WH + (size_t)(k0 + w_r) * HID + w_c);
        cpa16(&Wls[0][w_r][w_c], WL + (size_t)(k0 + w_r) * HID + w_c);
        CP_COMMIT();
    }

    for (int kc = 0; kc < 16; kc++) {
        const int buf = kc & 1;
        if (kc + 1 < 16) {
            const int nb = (kc + 1) & 1;
            const int k0 = (kc + 1) * 16;
            cpa16(&Ahs[nb][a_r][a_c], g_cath + (size_t)(row0 + a_r) * 256 + k0 + a_c);
            cpa16(&Als[nb][a_r][a_c], g_catl + (size_t)(row0 + a_r) * 256 + k0 + a_c);
            cpa16(&Whs[nb][w_r][w_c], WH + (size_t)(k0 + w_r) * HID + w_c);
            cpa16(&Wls[nb][w_r][w_c], WL + (size_t)(k0 + w_r) * HID + w_c);
            CP_COMMIT();
            asm volatile("cp.async.wait_group 1;");
        } else {
            asm volatile("cp.async.wait_group 0;");
        }
        __syncthreads();

        unsigned ah0[4], al0[4], ah1[4], al1[4];
        LDMX4(ah0, &Ahs[buf][wr * 32 + (lane & 15)][a_co]);
        LDMX4(al0, &Als[buf][wr * 32 + (lane & 15)][a_co]);
        LDMX4(ah1, &Ahs[buf][wr * 32 + 16 + (lane & 15)][a_co]);
        LDMX4(al1, &Als[buf][wr * 32 + 16 + (lane & 15)][a_co]);
#pragma unroll
        for (int t = 0; t < 4; t++) {
            unsigned bh[4], bl[4];
            LDMX4T(bh, &Whs[buf][b_kr][wc * 64 + t * 16 + b_no]);
            LDMX4T(bl, &Wls[buf][b_kr][wc * 64 + t * 16 + b_no]);
            mma16816(c[0][2 * t],     ah0, bh[0], bh[1]);
            mma16816(c[0][2 * t],     ah0, bl[0], bl[1]);
            mma16816(c[0][2 * t],     al0, bh[0], bh[1]);
            mma16816(c[0][2 * t + 1], ah0, bh[2], bh[3]);
            mma16816(c[0][2 * t + 1], ah0, bl[2], bl[3]);
            mma16816(c[0][2 * t + 1], al0, bh[2], bh[3]);
            mma16816(c[1][2 * t],     ah1, bh[0], bh[1]);
            mma16816(c[1][2 * t],     ah1, bl[0], bl[1]);
            mma16816(c[1][2 * t],     al1, bh[0], bh[1]);
            mma16816(c[1][2 * t + 1], ah1, bh[2], bh[3]);
            mma16816(c[1][2 * t + 1], ah1, bl[2], bl[3]);
            mma16816(c[1][2 * t + 1], al1, bh[2], bh[3]);
        }
        __syncthreads();
    }

    // epilogue
#pragma unroll
    for (int rf = 0; rf < 2; rf++) {
        int r0 = row0 + wr * 32 + rf * 16 + (lane >> 2);
        int r1 = r0 + 8;
        int g0 = 0, g1 = 0;
        if (POOL) {
            g0 = (r0 < N_NODES) ? batch[r0] : 0;
            g1 = (r1 < N_NODES) ? batch[r1] : 0;
        }
#pragma unroll
        for (int t2 = 0; t2 < 8; t2++) {
            int col = wc * 64 + t2 * 8 + (lane & 3) * 2;
            float bv0 = bias[col], bv1 = bias[col + 1];
            float v00 = c[rf][t2][0] + bv0, v01 = c[rf][t2][1] + bv1;
            float v10 = c[rf][t2][2] + bv0, v11 = c[rf][t2][3] + bv1;
            if (!POOL) {
                v00 = fmaxf(v00, 0.f); v01 = fmaxf(v01, 0.f);
                v10 = fmaxf(v10, 0.f); v11 = fmaxf(v11, 0.f);
                unsigned h0v, l0v, h1v, l1v;
                split2(v00, v01, h0v, l0v);
                split2(v10, v11, h1v, l1v);
                *(unsigned*)(g_cath + (size_t)r0 * 256 + 128 + col) = h0v;
                *(unsigned*)(g_catl + (size_t)r0 * 256 + 128 + col) = l0v;
                *(unsigned*)(g_cath + (size_t)r1 * 256 + 128 + col) = h1v;
                *(unsigned*)(g_catl + (size_t)r1 * 256 + 128 + col) = l1v;
            } else {
                if (r0 < N_NODES) {
                    atomicAdd(&g_pooled[(size_t)g0 * HID + col], v00);
                    atomicAdd(&g_pooled[(size_t)g0 * HID + col + 1], v01);
                }
                if (r1 < N_NODES) {
                    atomicAdd(&g_pooled[(size_t)g1 * HID + col], v10);
                    atomicAdd(&g_pooled[(size_t)g1 * HID + col + 1], v11);
                }
            }
        }
    }
}

// ---------------- final: mean pool -> linear -> sigmoid ----------------
__global__ void k_final(const float* __restrict__ Wlin, const float* __restrict__ blin,
                        float* __restrict__ out) {
    int g = blockIdx.x;
    int t = threadIdx.x;              // 128
    float cnt = fmaxf((float)g_cnt[g], 1.0f);
    float v = g_pooled[(size_t)g * HID + t] * (1.0f / cnt) * Wlin[t];
#pragma unroll
    for (int off = 16; off > 0; off >>= 1)
        v += __shfl_xor_sync(0xffffffffu, v, off);
    __shared__ float ws[4];
    if ((t & 31) == 0) ws[t >> 5] = v;
    __syncthreads();
    if (t == 0) {
        float s = ws[0] + ws[1] + ws[2] + ws[3] + blin[0];
        out[g] = 1.0f / (1.0f + expf(-s));
    }
}

// ---------------- launch ----------------
extern "C" void kernel_launch(void* const* d_in, const int* in_sizes, int n_in,
                              void* d_out, int out_size) {
    const float* x      = (const float*)d_in[0];
    const int*   ei     = (const int*)d_in[1];
    const int*   batch  = (const int*)d_in[2];
    const float* Wrel0  = (const float*)d_in[3];
    const float* brel0  = (const float*)d_in[4];
    const float* Wroot0 = (const float*)d_in[5];
    const float* Wrel1  = (const float*)d_in[6];
    const float* brel1  = (const float*)d_in[7];
    const float* Wroot1 = (const float*)d_in[8];
    const float* Wrel2  = (const float*)d_in[9];
    const float* brel2  = (const float*)d_in[10];
    const float* Wroot2 = (const float*)d_in[11];
    const float* Wlin   = (const float*)d_in[12];
    const float* blin   = (const float*)d_in[13];
    float* out = (float*)d_out;

    k_zero<<<(NUM_GRAPHS * HID + 255) / 256, 256>>>();
    k_histcnt<<<(N_EDGES + 255) / 256, 256>>>(ei, batch);
    k_wconv<<<(2 * 256 * HID + 255) / 256, 256>>>(Wrel1, Wroot1, Wrel2, Wroot2);
    k_scanA<<<NB, 256>>>();
    k_scanB<<<1, 256>>>();
    k_scanC<<<NB, 256>>>();
    k_scatter<<<(N_EDGES + 255) / 256, 256>>>(ei);

    // layer 0 (fused agg + linear + relu)
    k_l0<<<(N_NODES * 32 + 255) / 256, 256>>>(x, Wrel0, brel0, Wroot0);

    // layer 1
    k_gather<<<(N_NODES * 32 + 255) / 256, 256>>>();
    k_gemm<0><<<N_PAD / 128, 256>>>(brel1, batch);

    // layer 2 (+ fused pooling accumulate)
    k_gather<<<(N_NODES * 32 + 255) / 256, 256>>>();
    k_gemm<1><<<N_PAD / 128, 256>>>(brel2, batch);

    // head
    k_final<<<NUM_GRAPHS, HID>>>(Wlin, blin, out);
}